// round 9
// baseline (speedup 1.0000x reference)
#include <cuda_runtime.h>
#include <math.h>

// Problem constants
#define T_STEPS 256
#define BATCH   1024
#define SEG     64
#define HID     128
#define G4      512          // 4*HID
#define K0      192          // SEG + HID (layer 0 fused input)
#define K1      256          // HID + HID (layer 1)
#define R       8            // batch rows per CTA
#define NCTA    (BATCH / R)  // 128 CTAs
#define RPAD    10           // padded row stride for k-major SMEM tiles

// Gate-split weights: g_W?[p][k][j] = float2( w_{gate 2p}[n=2p*128+j][k],
//                                             w_{gate 2p+1}[n=(2p+1)*128+j][k] )
__device__ float2 g_W0[2 * K0 * HID];   // 393 KB
__device__ float2 g_W1[2 * K1 * HID];   // 524 KB
__device__ float  g_b0[G4];
__device__ float  g_b1[G4];

// ---------------------------------------------------------------------------
// Prep: fold prelstm into layer-0 input weights, split by gate pair.
//   k in [0,SEG)    : W0fold[n][k] = sum_h w_ih0[n][h] * pre_w[h][k]
//   k in [SEG,K0)   : w_hh0[n][k-SEG]
// ---------------------------------------------------------------------------
__device__ __forceinline__ float w0_val(int n, int k,
    const float* __restrict__ pre_w, const float* __restrict__ w_ih0,
    const float* __restrict__ w_hh0)
{
    if (k < SEG) {
        float s = 0.f;
        #pragma unroll 8
        for (int h = 0; h < HID; h++)
            s += w_ih0[n * HID + h] * pre_w[h * SEG + k];
        return s;
    }
    return w_hh0[n * HID + (k - SEG)];
}

__global__ void prep_kernel(
    const float* __restrict__ pre_w,  const float* __restrict__ pre_b,
    const float* __restrict__ w_ih0,  const float* __restrict__ w_hh0,
    const float* __restrict__ b_ih0,  const float* __restrict__ b_hh0,
    const float* __restrict__ w_ih1,  const float* __restrict__ w_hh1,
    const float* __restrict__ b_ih1,  const float* __restrict__ b_hh1)
{
    int idx = blockIdx.x * blockDim.x + threadIdx.x;
    int stride = gridDim.x * blockDim.x;

    for (int e = idx; e < 2 * K0 * HID; e += stride) {
        int p = e / (K0 * HID);
        int rem = e % (K0 * HID);
        int k = rem / HID;
        int j = rem % HID;
        int n0 = (2 * p) * HID + j;
        int n1 = (2 * p + 1) * HID + j;
        float2 v;
        v.x = w0_val(n0, k, pre_w, w_ih0, w_hh0);
        v.y = w0_val(n1, k, pre_w, w_ih0, w_hh0);
        g_W0[e] = v;
    }

    for (int e = idx; e < 2 * K1 * HID; e += stride) {
        int p = e / (K1 * HID);
        int rem = e % (K1 * HID);
        int k = rem / HID;
        int j = rem % HID;
        int n0 = (2 * p) * HID + j;
        int n1 = (2 * p + 1) * HID + j;
        float2 v;
        v.x = (k < HID) ? w_ih1[n0 * HID + k] : w_hh1[n0 * HID + (k - HID)];
        v.y = (k < HID) ? w_ih1[n1 * HID + k] : w_hh1[n1 * HID + (k - HID)];
        g_W1[e] = v;
    }

    for (int n = idx; n < G4; n += stride) {
        float s = 0.f;
        for (int h = 0; h < HID; h++)
            s += w_ih0[n * HID + h] * pre_b[h];
        g_b0[n] = s + b_ih0[n] + b_hh0[n];
        g_b1[n] = b_ih1[n] + b_hh1[n];
    }
}

// ---------------------------------------------------------------------------
// f32x2 packed helpers (sm_103 FFMA2 path — only reachable via PTX)
// ---------------------------------------------------------------------------
typedef unsigned long long u64;

__device__ __forceinline__ u64 pk2(float x, float y) {
    u64 r;
    asm("mov.b64 %0, {%1, %2};" : "=l"(r) : "f"(x), "f"(y));
    return r;
}
__device__ __forceinline__ void upk2(u64 v, float& x, float& y) {
    asm("mov.b64 {%0, %1}, %2;" : "=f"(x), "=f"(y) : "l"(v));
}
__device__ __forceinline__ void ffma2(u64& d, u64 a, u64 b) {
    asm("fma.rn.f32x2 %0, %1, %2, %0;" : "+l"(d) : "l"(a), "l"(b));
}

__device__ __forceinline__ float fsig(float x) {
    return __fdividef(1.f, 1.f + __expf(-x));
}
__device__ __forceinline__ float ftanh(float x) {
    return __fdividef(2.f, 1.f + __expf(-2.f * x)) - 1.f;
}

// ---------------------------------------------------------------------------
// Fused persistent LSTM. Grid: 128 CTAs x 256 threads.
// Thread (j = tid&127, p = tid>>7): hidden column j, gate pair p
// (p=0 -> gates i,f ; p=1 -> gates g,o), all 8 rows in the matvec
// (row-paired f32x2 accumulators), then state update for rows p*4..p*4+3.
// ---------------------------------------------------------------------------
__global__ __launch_bounds__(256, 1) void lstm_kernel(
    const float* __restrict__ x_in,   // [T, B, SEG]
    const float* __restrict__ h0in,   // [2, B, HID]
    const float* __restrict__ c0in,   // [2, B, HID]
    const float* __restrict__ post_w, // [1, HID]
    const float* __restrict__ post_b, // [1]
    float* __restrict__ out)          // pred[B] | h_t[2,B,H] | c_t[2,B,H]
{
    __shared__ __align__(16) float x_s[SEG * RPAD];   // [s][row]
    __shared__ __align__(16) float h0_s[HID * RPAD];  // [k][row]
    __shared__ __align__(16) float h1_s[HID * RPAD];  // [k][row]
    __shared__ __align__(16) float gsm[R * 4 * HID];  // [row][gate][j]

    const int tid  = threadIdx.x;
    const int j    = tid & (HID - 1);
    const int p    = tid >> 7;          // gate-pair / group id
    const int row0 = blockIdx.x * R;
    const int rb   = p * 4;             // local rows owned for state update

    float c0v[4], c1v[4], h0n[4], h1n[4];
    #pragma unroll
    for (int u = 0; u < 4; u++) {
        int b = row0 + rb + u;
        c0v[u] = c0in[0 * BATCH * HID + b * HID + j];
        c1v[u] = c0in[1 * BATCH * HID + b * HID + j];
        h0_s[j * RPAD + rb + u] = h0in[0 * BATCH * HID + b * HID + j];
        h1_s[j * RPAD + rb + u] = h0in[1 * BATCH * HID + b * HID + j];
    }
    __syncthreads();

    const float2* __restrict__ W0 = g_W0 + p * (K0 * HID) + j;
    const float2* __restrict__ W1 = g_W1 + p * (K1 * HID) + j;

    // packed (duplicated) biases for this thread's two gates
    const u64 bb0a = pk2(g_b0[(2 * p) * HID + j],     g_b0[(2 * p) * HID + j]);
    const u64 bb0b = pk2(g_b0[(2 * p + 1) * HID + j], g_b0[(2 * p + 1) * HID + j]);
    const u64 bb1a = pk2(g_b1[(2 * p) * HID + j],     g_b1[(2 * p) * HID + j]);
    const u64 bb1b = pk2(g_b1[(2 * p + 1) * HID + j], g_b1[(2 * p + 1) * HID + j]);

    for (int t = 0; t < T_STEPS; t++) {
        // Stage x_t: 512 floats, 2 per thread, k-major with row padding
        #pragma unroll
        for (int e = tid; e < R * SEG; e += 256) {
            int r = e >> 6;
            int s = e & 63;
            x_s[s * RPAD + r] = x_in[((long)t * BATCH + (row0 + r)) * SEG + s];
        }
        __syncthreads();

        // ================= layer 0 matvec =================
        u64 a0[4], a1[4];
        #pragma unroll
        for (int q = 0; q < 4; q++) { a0[q] = bb0a; a1[q] = bb0b; }

        #pragma unroll 4
        for (int k = 0; k < SEG; k++) {
            float2 w = W0[k * HID];
            u64 wa = pk2(w.x, w.x);
            u64 wb = pk2(w.y, w.y);
            #pragma unroll
            for (int q = 0; q < 4; q++) {
                u64 xv = *(const u64*)&x_s[k * RPAD + 2 * q];
                ffma2(a0[q], wa, xv);
                ffma2(a1[q], wb, xv);
            }
        }
        #pragma unroll 4
        for (int k = 0; k < HID; k++) {
            float2 w = W0[(SEG + k) * HID];
            u64 wa = pk2(w.x, w.x);
            u64 wb = pk2(w.y, w.y);
            #pragma unroll
            for (int q = 0; q < 4; q++) {
                u64 hv = *(const u64*)&h0_s[k * RPAD + 2 * q];
                ffma2(a0[q], wa, hv);
                ffma2(a1[q], wb, hv);
            }
        }

        // activations for my 2 gates, all 8 rows -> gsm[row][gate][j]
        #pragma unroll
        for (int q = 0; q < 4; q++) {
            float lo0, hi0, lo1, hi1;
            upk2(a0[q], lo0, hi0);
            upk2(a1[q], lo1, hi1);
            if (p == 0) {           // gates i, f : sigmoid
                lo0 = fsig(lo0); hi0 = fsig(hi0);
                lo1 = fsig(lo1); hi1 = fsig(hi1);
            } else {                // gates g (tanh), o (sigmoid)
                lo0 = ftanh(lo0); hi0 = ftanh(hi0);
                lo1 = fsig(lo1);  hi1 = fsig(hi1);
            }
            int r0 = 2 * q, r1 = 2 * q + 1;
            gsm[(r0 * 4 + 2 * p)     * HID + j] = lo0;
            gsm[(r1 * 4 + 2 * p)     * HID + j] = hi0;
            gsm[(r0 * 4 + 2 * p + 1) * HID + j] = lo1;
            gsm[(r1 * 4 + 2 * p + 1) * HID + j] = hi1;
        }
        __syncthreads();

        // state update for my 4 rows, publish new h0
        #pragma unroll
        for (int u = 0; u < 4; u++) {
            int r = rb + u;
            float ig = gsm[(r * 4 + 0) * HID + j];
            float fg = gsm[(r * 4 + 1) * HID + j];
            float gg = gsm[(r * 4 + 2) * HID + j];
            float og = gsm[(r * 4 + 3) * HID + j];
            c0v[u] = fg * c0v[u] + ig * gg;
            h0n[u] = og * ftanh(c0v[u]);
            h0_s[j * RPAD + r] = h0n[u];
        }
        __syncthreads();

        // ================= layer 1 matvec =================
        #pragma unroll
        for (int q = 0; q < 4; q++) { a0[q] = bb1a; a1[q] = bb1b; }

        #pragma unroll 4
        for (int k = 0; k < HID; k++) {
            float2 w = W1[k * HID];
            u64 wa = pk2(w.x, w.x);
            u64 wb = pk2(w.y, w.y);
            #pragma unroll
            for (int q = 0; q < 4; q++) {
                u64 hv = *(const u64*)&h0_s[k * RPAD + 2 * q];
                ffma2(a0[q], wa, hv);
                ffma2(a1[q], wb, hv);
            }
        }
        #pragma unroll 4
        for (int k = 0; k < HID; k++) {
            float2 w = W1[(HID + k) * HID];
            u64 wa = pk2(w.x, w.x);
            u64 wb = pk2(w.y, w.y);
            #pragma unroll
            for (int q = 0; q < 4; q++) {
                u64 hv = *(const u64*)&h1_s[k * RPAD + 2 * q];
                ffma2(a0[q], wa, hv);
                ffma2(a1[q], wb, hv);
            }
        }

        #pragma unroll
        for (int q = 0; q < 4; q++) {
            float lo0, hi0, lo1, hi1;
            upk2(a0[q], lo0, hi0);
            upk2(a1[q], lo1, hi1);
            if (p == 0) {
                lo0 = fsig(lo0); hi0 = fsig(hi0);
                lo1 = fsig(lo1); hi1 = fsig(hi1);
            } else {
                lo0 = ftanh(lo0); hi0 = ftanh(hi0);
                lo1 = fsig(lo1);  hi1 = fsig(hi1);
            }
            int r0 = 2 * q, r1 = 2 * q + 1;
            gsm[(r0 * 4 + 2 * p)     * HID + j] = lo0;
            gsm[(r1 * 4 + 2 * p)     * HID + j] = hi0;
            gsm[(r0 * 4 + 2 * p + 1) * HID + j] = lo1;
            gsm[(r1 * 4 + 2 * p + 1) * HID + j] = hi1;
        }
        __syncthreads();

        #pragma unroll
        for (int u = 0; u < 4; u++) {
            int r = rb + u;
            float ig = gsm[(r * 4 + 0) * HID + j];
            float fg = gsm[(r * 4 + 1) * HID + j];
            float gg = gsm[(r * 4 + 2) * HID + j];
            float og = gsm[(r * 4 + 3) * HID + j];
            c1v[u] = fg * c1v[u] + ig * gg;
            h1n[u] = og * ftanh(c1v[u]);
            h1_s[j * RPAD + r] = h1n[u];
        }
        __syncthreads();   // also orders h1/gsm for next iteration
    }

    // ---------------- outputs ----------------
    const int OH = BATCH;                    // h_t offset
    const int OC = BATCH + 2 * BATCH * HID;  // c_t offset
    #pragma unroll
    for (int u = 0; u < 4; u++) {
        int b = row0 + rb + u;
        out[OH + 0 * BATCH * HID + b * HID + j] = h0n[u];
        out[OH + 1 * BATCH * HID + b * HID + j] = h1n[u];
        out[OC + 0 * BATCH * HID + b * HID + j] = c0v[u];
        out[OC + 1 * BATCH * HID + b * HID + j] = c1v[u];
    }

    // pred: one warp per row, shuffle reduce over relu(h1)*post_w
    int w    = tid >> 5;   // 8 warps = 8 rows
    int lane = tid & 31;
    float s = 0.f;
    #pragma unroll
    for (int jj = lane; jj < HID; jj += 32) {
        float hv = fmaxf(h1_s[jj * RPAD + w], 0.f);
        s += hv * post_w[jj];
    }
    #pragma unroll
    for (int off = 16; off; off >>= 1)
        s += __shfl_xor_sync(0xffffffffu, s, off);
    if (lane == 0)
        out[row0 + w] = s + post_b[0];
}

extern "C" void kernel_launch(void* const* d_in, const int* in_sizes, int n_in,
                              void* d_out, int out_size)
{
    const float* x_in   = (const float*)d_in[0];
    const float* h0     = (const float*)d_in[1];
    const float* c0     = (const float*)d_in[2];
    const float* pre_w  = (const float*)d_in[3];
    const float* pre_b  = (const float*)d_in[4];
    const float* w_ih0  = (const float*)d_in[5];
    const float* w_hh0  = (const float*)d_in[6];
    const float* b_ih0  = (const float*)d_in[7];
    const float* b_hh0  = (const float*)d_in[8];
    const float* w_ih1  = (const float*)d_in[9];
    const float* w_hh1  = (const float*)d_in[10];
    const float* b_ih1  = (const float*)d_in[11];
    const float* b_hh1  = (const float*)d_in[12];
    const float* post_w = (const float*)d_in[13];
    const float* post_b = (const float*)d_in[14];
    float* out = (float*)d_out;

    prep_kernel<<<192, 256>>>(pre_w, pre_b, w_ih0, w_hh0, b_ih0, b_hh0,
                              w_ih1, w_hh1, b_ih1, b_hh1);
    lstm_kernel<<<NCTA, 256>>>(x_in, h0, c0, post_w, post_b, out);
}

// round 11
// speedup vs baseline: 1.1670x; 1.1670x over previous
#include <cuda_runtime.h>
#include <math.h>

// Problem constants
#define T_STEPS 256
#define BATCH   1024
#define SEG     64
#define HID     128
#define G4      512          // 4*HID
#define K0      192          // SEG + HID (layer 0 fused input)
#define K1      256          // HID + HID (layer 1)
#define R       8            // batch rows per CTA
#define NCTA    (BATCH / R)  // 128 CTAs
#define NTHR    512          // threads per CTA
#define RPAD    10           // padded row stride (even -> 8B-aligned float2)

// Preprocessed weights, gate-interleaved: g_Wc[(k*HID + j)*4 + g]
// so thread j loads one float4 = the 4 gate weights for (k, j).
__device__ float g_Wc0[K0 * HID * 4];   // 393 KB
__device__ float g_Wc1[K1 * HID * 4];   // 524 KB
__device__ float g_b0[G4];
__device__ float g_b1[G4];

// ---------------------------------------------------------------------------
// Prep: fold prelstm into layer-0 input weights, interleave gate columns.
//   gates0 = x_in @ W0^T + h @ w_hh0^T + (w_ih0@pre_b + b_ih0 + b_hh0)
//   W0 = w_ih0 @ pre_w  : [512, 64]
// ---------------------------------------------------------------------------
__global__ void prep_kernel(
    const float* __restrict__ pre_w,  const float* __restrict__ pre_b,
    const float* __restrict__ w_ih0,  const float* __restrict__ w_hh0,
    const float* __restrict__ b_ih0,  const float* __restrict__ b_hh0,
    const float* __restrict__ w_ih1,  const float* __restrict__ w_hh1,
    const float* __restrict__ b_ih1,  const float* __restrict__ b_hh1)
{
    int idx = blockIdx.x * blockDim.x + threadIdx.x;
    int stride = gridDim.x * blockDim.x;

    for (int e = idx; e < K0 * G4; e += stride) {
        int k = e / G4;
        int n = e % G4;
        int g = n / HID;
        int j = n % HID;
        float v;
        if (k < SEG) {
            float s = 0.f;
            #pragma unroll 8
            for (int h = 0; h < HID; h++)
                s += w_ih0[n * HID + h] * pre_w[h * SEG + k];
            v = s;
        } else {
            v = w_hh0[n * HID + (k - SEG)];
        }
        g_Wc0[(k * HID + j) * 4 + g] = v;
    }

    for (int e = idx; e < K1 * G4; e += stride) {
        int k = e / G4;
        int n = e % G4;
        int g = n / HID;
        int j = n % HID;
        float v = (k < HID) ? w_ih1[n * HID + k] : w_hh1[n * HID + (k - HID)];
        g_Wc1[(k * HID + j) * 4 + g] = v;
    }

    for (int n = idx; n < G4; n += stride) {
        float s = 0.f;
        for (int h = 0; h < HID; h++)
            s += w_ih0[n * HID + h] * pre_b[h];
        g_b0[n] = s + b_ih0[n] + b_hh0[n];
        g_b1[n] = b_ih1[n] + b_hh1[n];
    }
}

__device__ __forceinline__ float fsig(float x) {
    return __fdividef(1.f, 1.f + __expf(-x));
}
__device__ __forceinline__ float ftanh(float x) {
    return __fdividef(2.f, 1.f + __expf(-2.f * x)) - 1.f;
}

// ---------------------------------------------------------------------------
// Fused persistent LSTM. Grid: 128 CTAs x 512 threads (16 warps/SM).
// Thread (j = tid&127, rg = tid>>7): hidden column j, batch rows
// rg*2 .. rg*2+1, all 4 gates. x/h staged k-major so the per-k operand
// for both rows is ONE LDS.64 broadcast.
// ---------------------------------------------------------------------------
__global__ __launch_bounds__(NTHR, 1) void lstm_kernel(
    const float* __restrict__ x_in,   // [T, B, SEG]
    const float* __restrict__ h0in,   // [2, B, HID]
    const float* __restrict__ c0in,   // [2, B, HID]
    const float* __restrict__ post_w, // [1, HID]
    const float* __restrict__ post_b, // [1]
    float* __restrict__ out)          // pred[B] | h_t[2,B,H] | c_t[2,B,H]
{
    __shared__ __align__(16) float x_s[SEG * RPAD];   // [s][row]
    __shared__ __align__(16) float h0_s[HID * RPAD];  // [k][row]
    __shared__ __align__(16) float h1_s[HID * RPAD];  // [k][row]

    const int tid  = threadIdx.x;
    const int j    = tid & (HID - 1);
    const int rg   = tid >> 7;          // row group 0..3
    const int rb   = rg * 2;            // local row base (2 rows per thread)
    const int row0 = blockIdx.x * R;

    float c0v[2], c1v[2], h0n[2], h1n[2];
    #pragma unroll
    for (int u = 0; u < 2; u++) {
        int b = row0 + rb + u;
        c0v[u] = c0in[0 * BATCH * HID + b * HID + j];
        c1v[u] = c0in[1 * BATCH * HID + b * HID + j];
        h0_s[j * RPAD + rb + u] = h0in[0 * BATCH * HID + b * HID + j];
        h1_s[j * RPAD + rb + u] = h0in[1 * BATCH * HID + b * HID + j];
    }
    __syncthreads();

    const float4* __restrict__ W0p = (const float4*)g_Wc0;  // [K0*HID] float4
    const float4* __restrict__ W1p = (const float4*)g_Wc1;  // [K1*HID] float4

    float b0g[4], b1g[4];
    #pragma unroll
    for (int g = 0; g < 4; g++) {
        b0g[g] = g_b0[g * HID + j];
        b1g[g] = g_b1[g * HID + j];
    }

    for (int t = 0; t < T_STEPS; t++) {
        // Stage x_t: 512 floats, 1 per thread, k-major with padded row stride
        {
            int r = tid >> 6;          // 0..7
            int s = tid & 63;          // 0..63
            x_s[s * RPAD + r] = x_in[((long)t * BATCH + (row0 + r)) * SEG + s];
        }
        __syncthreads();

        // ================= layer 0 =================
        float acc[4][2];
        #pragma unroll
        for (int g = 0; g < 4; g++) {
            acc[g][0] = b0g[g];
            acc[g][1] = b0g[g];
        }

        #pragma unroll 8
        for (int k = 0; k < SEG; k++) {
            float4 w = W0p[k * HID + j];
            float2 xv = *(const float2*)&x_s[k * RPAD + rb];
            acc[0][0] = fmaf(w.x, xv.x, acc[0][0]);
            acc[0][1] = fmaf(w.x, xv.y, acc[0][1]);
            acc[1][0] = fmaf(w.y, xv.x, acc[1][0]);
            acc[1][1] = fmaf(w.y, xv.y, acc[1][1]);
            acc[2][0] = fmaf(w.z, xv.x, acc[2][0]);
            acc[2][1] = fmaf(w.z, xv.y, acc[2][1]);
            acc[3][0] = fmaf(w.w, xv.x, acc[3][0]);
            acc[3][1] = fmaf(w.w, xv.y, acc[3][1]);
        }
        #pragma unroll 8
        for (int k = 0; k < HID; k++) {
            float4 w = W0p[(SEG + k) * HID + j];
            float2 hv = *(const float2*)&h0_s[k * RPAD + rb];
            acc[0][0] = fmaf(w.x, hv.x, acc[0][0]);
            acc[0][1] = fmaf(w.x, hv.y, acc[0][1]);
            acc[1][0] = fmaf(w.y, hv.x, acc[1][0]);
            acc[1][1] = fmaf(w.y, hv.y, acc[1][1]);
            acc[2][0] = fmaf(w.z, hv.x, acc[2][0]);
            acc[2][1] = fmaf(w.z, hv.y, acc[2][1]);
            acc[3][0] = fmaf(w.w, hv.x, acc[3][0]);
            acc[3][1] = fmaf(w.w, hv.y, acc[3][1]);
        }
        #pragma unroll
        for (int u = 0; u < 2; u++) {
            float ig = fsig(acc[0][u]);
            float fg = fsig(acc[1][u]);
            float gg = ftanh(acc[2][u]);
            float og = fsig(acc[3][u]);
            c0v[u] = fg * c0v[u] + ig * gg;
            h0n[u] = og * ftanh(c0v[u]);
        }
        __syncthreads();              // all reads of h0_s done
        #pragma unroll
        for (int u = 0; u < 2; u++)
            h0_s[j * RPAD + rb + u] = h0n[u];
        __syncthreads();

        // ================= layer 1 =================
        #pragma unroll
        for (int g = 0; g < 4; g++) {
            acc[g][0] = b1g[g];
            acc[g][1] = b1g[g];
        }

        #pragma unroll 8
        for (int k = 0; k < HID; k++) {
            float4 w = W1p[k * HID + j];
            float2 hv = *(const float2*)&h0_s[k * RPAD + rb];   // new h0_t
            acc[0][0] = fmaf(w.x, hv.x, acc[0][0]);
            acc[0][1] = fmaf(w.x, hv.y, acc[0][1]);
            acc[1][0] = fmaf(w.y, hv.x, acc[1][0]);
            acc[1][1] = fmaf(w.y, hv.y, acc[1][1]);
            acc[2][0] = fmaf(w.z, hv.x, acc[2][0]);
            acc[2][1] = fmaf(w.z, hv.y, acc[2][1]);
            acc[3][0] = fmaf(w.w, hv.x, acc[3][0]);
            acc[3][1] = fmaf(w.w, hv.y, acc[3][1]);
        }
        #pragma unroll 8
        for (int k = 0; k < HID; k++) {
            float4 w = W1p[(HID + k) * HID + j];
            float2 hv = *(const float2*)&h1_s[k * RPAD + rb];   // previous h1
            acc[0][0] = fmaf(w.x, hv.x, acc[0][0]);
            acc[0][1] = fmaf(w.x, hv.y, acc[0][1]);
            acc[1][0] = fmaf(w.y, hv.x, acc[1][0]);
            acc[1][1] = fmaf(w.y, hv.y, acc[1][1]);
            acc[2][0] = fmaf(w.z, hv.x, acc[2][0]);
            acc[2][1] = fmaf(w.z, hv.y, acc[2][1]);
            acc[3][0] = fmaf(w.w, hv.x, acc[3][0]);
            acc[3][1] = fmaf(w.w, hv.y, acc[3][1]);
        }
        #pragma unroll
        for (int u = 0; u < 2; u++) {
            float ig = fsig(acc[0][u]);
            float fg = fsig(acc[1][u]);
            float gg = ftanh(acc[2][u]);
            float og = fsig(acc[3][u]);
            c1v[u] = fg * c1v[u] + ig * gg;
            h1n[u] = og * ftanh(c1v[u]);
        }
        __syncthreads();              // all reads of h1_s done
        #pragma unroll
        for (int u = 0; u < 2; u++)
            h1_s[j * RPAD + rb + u] = h1n[u];
        __syncthreads();
    }

    // ---------------- outputs ----------------
    const int OH = BATCH;                    // h_t offset
    const int OC = BATCH + 2 * BATCH * HID;  // c_t offset
    #pragma unroll
    for (int u = 0; u < 2; u++) {
        int b = row0 + rb + u;
        out[OH + 0 * BATCH * HID + b * HID + j] = h0n[u];
        out[OH + 1 * BATCH * HID + b * HID + j] = h1n[u];
        out[OC + 0 * BATCH * HID + b * HID + j] = c0v[u];
        out[OC + 1 * BATCH * HID + b * HID + j] = c1v[u];
    }

    // pred: warps 0..7, one warp per row, shuffle reduce over relu(h1)*post_w
    if (tid < 256) {
        int w    = tid >> 5;   // row 0..7
        int lane = tid & 31;
        float s = 0.f;
        #pragma unroll
        for (int jj = lane; jj < HID; jj += 32) {
            float hv = fmaxf(h1_s[jj * RPAD + w], 0.f);
            s += hv * post_w[jj];
        }
        #pragma unroll
        for (int off = 16; off; off >>= 1)
            s += __shfl_xor_sync(0xffffffffu, s, off);
        if (lane == 0)
            out[row0 + w] = s + post_b[0];
    }
}

extern "C" void kernel_launch(void* const* d_in, const int* in_sizes, int n_in,
                              void* d_out, int out_size)
{
    const float* x_in   = (const float*)d_in[0];
    const float* h0     = (const float*)d_in[1];
    const float* c0     = (const float*)d_in[2];
    const float* pre_w  = (const float*)d_in[3];
    const float* pre_b  = (const float*)d_in[4];
    const float* w_ih0  = (const float*)d_in[5];
    const float* w_hh0  = (const float*)d_in[6];
    const float* b_ih0  = (const float*)d_in[7];
    const float* b_hh0  = (const float*)d_in[8];
    const float* w_ih1  = (const float*)d_in[9];
    const float* w_hh1  = (const float*)d_in[10];
    const float* b_ih1  = (const float*)d_in[11];
    const float* b_hh1  = (const float*)d_in[12];
    const float* post_w = (const float*)d_in[13];
    const float* post_b = (const float*)d_in[14];
    float* out = (float*)d_out;

    prep_kernel<<<192, 256>>>(pre_w, pre_b, w_ih0, w_hh0, b_ih0, b_hh0,
                              w_ih1, w_hh1, b_ih1, b_hh1);
    lstm_kernel<<<NCTA, NTHR>>>(x_in, h0, c0, post_w, post_b, out);
}

// round 12
// speedup vs baseline: 1.2601x; 1.0798x over previous
#include <cuda_runtime.h>
#include <math.h>

// Problem constants
#define T_STEPS 256
#define BATCH   1024
#define SEG     64
#define HID     128
#define G4      512          // 4*HID
#define K0      192          // SEG + HID (layer 0 fused input)
#define K1      256          // HID + HID (layer 1)
#define R       8            // batch rows per CTA
#define NCTA    (BATCH / R)  // 128 CTAs
#define NTHR    512          // threads per CTA (4 gate groups x 128 j)
#define RPAD    12           // padded row stride (48B: float4 at +0 and +16 aligned)

// Per-gate weight planes: g_W0g[g][k][j] = W[n = g*128+j][k]
__device__ float g_W0g[4 * K0 * HID];   // 393 KB
__device__ float g_W1g[4 * K1 * HID];   // 524 KB
__device__ float g_b0[G4];
__device__ float g_b1[G4];

// ---------------------------------------------------------------------------
// Prep: fold prelstm into layer-0 input weights, split by gate.
//   k in [0,SEG)  : W0fold[n][k] = sum_h w_ih0[n][h] * pre_w[h][k]
//   k in [SEG,K0) : w_hh0[n][k-SEG]
// ---------------------------------------------------------------------------
__global__ void prep_kernel(
    const float* __restrict__ pre_w,  const float* __restrict__ pre_b,
    const float* __restrict__ w_ih0,  const float* __restrict__ w_hh0,
    const float* __restrict__ b_ih0,  const float* __restrict__ b_hh0,
    const float* __restrict__ w_ih1,  const float* __restrict__ w_hh1,
    const float* __restrict__ b_ih1,  const float* __restrict__ b_hh1)
{
    int idx = blockIdx.x * blockDim.x + threadIdx.x;
    int stride = gridDim.x * blockDim.x;

    for (int e = idx; e < 4 * K0 * HID; e += stride) {
        int g = e / (K0 * HID);
        int rem = e % (K0 * HID);
        int k = rem / HID;
        int j = rem % HID;
        int n = g * HID + j;
        float v;
        if (k < SEG) {
            float s = 0.f;
            #pragma unroll 8
            for (int h = 0; h < HID; h++)
                s += w_ih0[n * HID + h] * pre_w[h * SEG + k];
            v = s;
        } else {
            v = w_hh0[n * HID + (k - SEG)];
        }
        g_W0g[e] = v;
    }

    for (int e = idx; e < 4 * K1 * HID; e += stride) {
        int g = e / (K1 * HID);
        int rem = e % (K1 * HID);
        int k = rem / HID;
        int j = rem % HID;
        int n = g * HID + j;
        g_W1g[e] = (k < HID) ? w_ih1[n * HID + k] : w_hh1[n * HID + (k - HID)];
    }

    for (int n = idx; n < G4; n += stride) {
        float s = 0.f;
        for (int h = 0; h < HID; h++)
            s += w_ih0[n * HID + h] * pre_b[h];
        g_b0[n] = s + b_ih0[n] + b_hh0[n];
        g_b1[n] = b_ih1[n] + b_hh1[n];
    }
}

__device__ __forceinline__ float fsig(float x) {
    return __fdividef(1.f, 1.f + __expf(-x));
}
__device__ __forceinline__ float ftanh(float x) {
    return __fdividef(2.f, 1.f + __expf(-2.f * x)) - 1.f;
}

// ---------------------------------------------------------------------------
// Fused persistent LSTM. Grid: 128 CTAs x 512 threads.
// Thread (j = tid&127, g = tid>>7): hidden column j, gate g (i,f,g,o),
// ALL 8 rows in the matvec (scalar weight load -> 1 cache line per warp,
// zero redundancy across groups). Gate exchange via SMEM, state update of
// rows 2g..2g+1 per thread.
// ---------------------------------------------------------------------------
__global__ __launch_bounds__(NTHR, 1) void lstm_kernel(
    const float* __restrict__ x_in,   // [T, B, SEG]
    const float* __restrict__ h0in,   // [2, B, HID]
    const float* __restrict__ c0in,   // [2, B, HID]
    const float* __restrict__ post_w, // [1, HID]
    const float* __restrict__ post_b, // [1]
    float* __restrict__ out)          // pred[B] | h_t[2,B,H] | c_t[2,B,H]
{
    __shared__ __align__(16) float x_s[SEG * RPAD];    // [s][row]
    __shared__ __align__(16) float h0_s[HID * RPAD];   // [k][row]
    __shared__ __align__(16) float h1_s[HID * RPAD];   // [k][row]
    __shared__ __align__(16) float gsm[4 * R * HID];   // [gate][row][j]

    const int tid  = threadIdx.x;
    const int j    = tid & (HID - 1);
    const int g    = tid >> 7;          // gate id 0..3 (i,f,g,o)
    const int row0 = blockIdx.x * R;
    const int r0   = 2 * g;             // rows owned for state update

    float c0v[2], c1v[2], h0n[2], h1n[2];
    #pragma unroll
    for (int u = 0; u < 2; u++) {
        int b = row0 + r0 + u;
        c0v[u] = c0in[0 * BATCH * HID + b * HID + j];
        c1v[u] = c0in[1 * BATCH * HID + b * HID + j];
        h0_s[j * RPAD + r0 + u] = h0in[0 * BATCH * HID + b * HID + j];
        h1_s[j * RPAD + r0 + u] = h0in[1 * BATCH * HID + b * HID + j];
    }
    __syncthreads();

    const float* __restrict__ W0 = g_W0g + g * (K0 * HID) + j;
    const float* __restrict__ W1 = g_W1g + g * (K1 * HID) + j;
    const float bias0 = g_b0[g * HID + j];
    const float bias1 = g_b1[g * HID + j];

    for (int t = 0; t < T_STEPS; t++) {
        // Stage x_t: 512 floats, 1 per thread, k-major padded
        {
            int r = tid >> 6;          // 0..7
            int s = tid & 63;          // 0..63
            x_s[s * RPAD + r] = x_in[((long)t * BATCH + (row0 + r)) * SEG + s];
        }
        __syncthreads();

        // ================= layer 0 matvec (my gate, 8 rows) =================
        float acc[8];
        #pragma unroll
        for (int r = 0; r < 8; r++) acc[r] = bias0;

        #pragma unroll 8
        for (int k = 0; k < SEG; k++) {
            float w = W0[k * HID];
            float4 lo = *(const float4*)&x_s[k * RPAD];
            float4 hi = *(const float4*)&x_s[k * RPAD + 4];
            acc[0] = fmaf(w, lo.x, acc[0]);
            acc[1] = fmaf(w, lo.y, acc[1]);
            acc[2] = fmaf(w, lo.z, acc[2]);
            acc[3] = fmaf(w, lo.w, acc[3]);
            acc[4] = fmaf(w, hi.x, acc[4]);
            acc[5] = fmaf(w, hi.y, acc[5]);
            acc[6] = fmaf(w, hi.z, acc[6]);
            acc[7] = fmaf(w, hi.w, acc[7]);
        }
        #pragma unroll 8
        for (int k = 0; k < HID; k++) {
            float w = W0[(SEG + k) * HID];
            float4 lo = *(const float4*)&h0_s[k * RPAD];
            float4 hi = *(const float4*)&h0_s[k * RPAD + 4];
            acc[0] = fmaf(w, lo.x, acc[0]);
            acc[1] = fmaf(w, lo.y, acc[1]);
            acc[2] = fmaf(w, lo.z, acc[2]);
            acc[3] = fmaf(w, lo.w, acc[3]);
            acc[4] = fmaf(w, hi.x, acc[4]);
            acc[5] = fmaf(w, hi.y, acc[5]);
            acc[6] = fmaf(w, hi.z, acc[6]);
            acc[7] = fmaf(w, hi.w, acc[7]);
        }
        // activation (uniform per warp: g is constant within a warp)
        if (g == 2) {
            #pragma unroll
            for (int r = 0; r < 8; r++) acc[r] = ftanh(acc[r]);
        } else {
            #pragma unroll
            for (int r = 0; r < 8; r++) acc[r] = fsig(acc[r]);
        }
        #pragma unroll
        for (int r = 0; r < 8; r++)
            gsm[(g * R + r) * HID + j] = acc[r];
        __syncthreads();

        // state update rows 2g, 2g+1; publish new h0
        #pragma unroll
        for (int u = 0; u < 2; u++) {
            int r = r0 + u;
            float ig = gsm[(0 * R + r) * HID + j];
            float fg = gsm[(1 * R + r) * HID + j];
            float gg = gsm[(2 * R + r) * HID + j];
            float og = gsm[(3 * R + r) * HID + j];
            c0v[u] = fg * c0v[u] + ig * gg;
            h0n[u] = og * ftanh(c0v[u]);
            h0_s[j * RPAD + r] = h0n[u];
        }
        __syncthreads();

        // ================= layer 1 matvec =================
        #pragma unroll
        for (int r = 0; r < 8; r++) acc[r] = bias1;

        #pragma unroll 8
        for (int k = 0; k < HID; k++) {
            float w = W1[k * HID];
            float4 lo = *(const float4*)&h0_s[k * RPAD];      // new h0_t
            float4 hi = *(const float4*)&h0_s[k * RPAD + 4];
            acc[0] = fmaf(w, lo.x, acc[0]);
            acc[1] = fmaf(w, lo.y, acc[1]);
            acc[2] = fmaf(w, lo.z, acc[2]);
            acc[3] = fmaf(w, lo.w, acc[3]);
            acc[4] = fmaf(w, hi.x, acc[4]);
            acc[5] = fmaf(w, hi.y, acc[5]);
            acc[6] = fmaf(w, hi.z, acc[6]);
            acc[7] = fmaf(w, hi.w, acc[7]);
        }
        #pragma unroll 8
        for (int k = 0; k < HID; k++) {
            float w = W1[(HID + k) * HID];
            float4 lo = *(const float4*)&h1_s[k * RPAD];      // previous h1
            float4 hi = *(const float4*)&h1_s[k * RPAD + 4];
            acc[0] = fmaf(w, lo.x, acc[0]);
            acc[1] = fmaf(w, lo.y, acc[1]);
            acc[2] = fmaf(w, lo.z, acc[2]);
            acc[3] = fmaf(w, lo.w, acc[3]);
            acc[4] = fmaf(w, hi.x, acc[4]);
            acc[5] = fmaf(w, hi.y, acc[5]);
            acc[6] = fmaf(w, hi.z, acc[6]);
            acc[7] = fmaf(w, hi.w, acc[7]);
        }
        if (g == 2) {
            #pragma unroll
            for (int r = 0; r < 8; r++) acc[r] = ftanh(acc[r]);
        } else {
            #pragma unroll
            for (int r = 0; r < 8; r++) acc[r] = fsig(acc[r]);
        }
        #pragma unroll
        for (int r = 0; r < 8; r++)
            gsm[(g * R + r) * HID + j] = acc[r];
        __syncthreads();

        #pragma unroll
        for (int u = 0; u < 2; u++) {
            int r = r0 + u;
            float ig = gsm[(0 * R + r) * HID + j];
            float fg = gsm[(1 * R + r) * HID + j];
            float gg = gsm[(2 * R + r) * HID + j];
            float og = gsm[(3 * R + r) * HID + j];
            c1v[u] = fg * c1v[u] + ig * gg;
            h1n[u] = og * ftanh(c1v[u]);
            h1_s[j * RPAD + r] = h1n[u];
        }
        __syncthreads();   // protects h1_s and gsm for next iteration
    }

    // ---------------- outputs ----------------
    const int OH = BATCH;                    // h_t offset
    const int OC = BATCH + 2 * BATCH * HID;  // c_t offset
    #pragma unroll
    for (int u = 0; u < 2; u++) {
        int b = row0 + r0 + u;
        out[OH + 0 * BATCH * HID + b * HID + j] = h0n[u];
        out[OH + 1 * BATCH * HID + b * HID + j] = h1n[u];
        out[OC + 0 * BATCH * HID + b * HID + j] = c0v[u];
        out[OC + 1 * BATCH * HID + b * HID + j] = c1v[u];
    }

    // pred: warps 0..7, one warp per row, shuffle reduce over relu(h1)*post_w
    if (tid < 256) {
        int w    = tid >> 5;   // row 0..7
        int lane = tid & 31;
        float s = 0.f;
        #pragma unroll
        for (int jj = lane; jj < HID; jj += 32) {
            float hv = fmaxf(h1_s[jj * RPAD + w], 0.f);
            s += hv * post_w[jj];
        }
        #pragma unroll
        for (int off = 16; off; off >>= 1)
            s += __shfl_xor_sync(0xffffffffu, s, off);
        if (lane == 0)
            out[row0 + w] = s + post_b[0];
    }
}

extern "C" void kernel_launch(void* const* d_in, const int* in_sizes, int n_in,
                              void* d_out, int out_size)
{
    const float* x_in   = (const float*)d_in[0];
    const float* h0     = (const float*)d_in[1];
    const float* c0     = (const float*)d_in[2];
    const float* pre_w  = (const float*)d_in[3];
    const float* pre_b  = (const float*)d_in[4];
    const float* w_ih0  = (const float*)d_in[5];
    const float* w_hh0  = (const float*)d_in[6];
    const float* b_ih0  = (const float*)d_in[7];
    const float* b_hh0  = (const float*)d_in[8];
    const float* w_ih1  = (const float*)d_in[9];
    const float* w_hh1  = (const float*)d_in[10];
    const float* b_ih1  = (const float*)d_in[11];
    const float* b_hh1  = (const float*)d_in[12];
    const float* post_w = (const float*)d_in[13];
    const float* post_b = (const float*)d_in[14];
    float* out = (float*)d_out;

    prep_kernel<<<192, 256>>>(pre_w, pre_b, w_ih0, w_hh0, b_ih0, b_hh0,
                              w_ih1, w_hh1, b_ih1, b_hh1);
    lstm_kernel<<<NCTA, NTHR>>>(x_in, h0, c0, post_w, post_b, out);
}